// round 7
// baseline (speedup 1.0000x reference)
#include <cuda_runtime.h>
#include <cuda_bf16.h>
#include <cstdint>

// MaxUnpooling2DMod: out[b, y(idx), x(idx), c] += in[b,h,w,c]
//   in  [8,128,128,64] -> 2^23 floats, out [8,256,256,64] -> 2^25 floats
// decode: out_off = (b << 22) + (idx & ~63) + (lin & 63)
//
// Persistent single-wave pipeline, ONE kernel:
//   every block, stage s: zero chunk of slab s -> release ready[s];
//                         load batch s-1 -> acquire ready[s-1]==GRID -> 4 REDG.
// GRID=1024 blocks, all guaranteed co-resident (launch_bounds(256,8) => <=32
// regs => 8 blocks/SM; 148 SM * 8 = 1184 >= 1024) => spins are benign.
// REDGs are fire-and-forget: stage-s atomics drain under stage-(s+1) zeros.

static constexpr int BLOCK    = 256;
static constexpr int GRID     = 1024;
static constexpr int THREADS  = GRID * BLOCK;          // 262144
static constexpr int SLAB_F4  = (1 << 22) / 4;         // 1,048,576 float4/slab
static constexpr int ZERO_PER_T = SLAB_F4 / THREADS;   // 4

__device__ unsigned g_ready[8];

__global__ void reset_counters_kernel()
{
    if (threadIdx.x < 8) g_ready[threadIdx.x] = 0;
}

__global__ void __launch_bounds__(BLOCK, 8)
unpool_persistent_kernel(const float* __restrict__ in,
                         const int*   __restrict__ idx,
                         float*       __restrict__ out)
{
    const int t = blockIdx.x * BLOCK + threadIdx.x;    // 0..262143

    #pragma unroll 1
    for (int s = 0; s <= 8; s++) {
        // ---- zero my chunk of slab s (no dependency) ----
        if (s < 8) {
            float4* o4 = reinterpret_cast<float4*>(out) + (size_t)s * SLAB_F4;
            const float4 z = make_float4(0.f, 0.f, 0.f, 0.f);
            #pragma unroll
            for (int j = 0; j < ZERO_PER_T; j++)
                o4[t + j * THREADS] = z;
            __syncthreads();                           // block's stores issued
            if (threadIdx.x == 0)
                asm volatile("red.release.gpu.global.add.u32 [%0], 1;"
                             :: "l"(&g_ready[s]) : "memory");
        }

        // ---- scatter batch s-1 ----
        if (s >= 1) {
            const int b  = s - 1;
            const int e0 = (b << 20) + (t << 2);       // my quad of 4 elems
            // loads issued before the spin: latency hidden under the wait
            const float4 v  = __ldcs(reinterpret_cast<const float4*>(in)  + (e0 >> 2));
            const int4   id = __ldcs(reinterpret_cast<const int4*>(idx)   + (e0 >> 2));

            if (threadIdx.x == 0) {
                const unsigned* p = &g_ready[b];
                unsigned c;
                do {
                    asm volatile("ld.acquire.gpu.global.u32 %0, [%1];"
                                 : "=r"(c) : "l"(p) : "memory");
                    if (c >= (unsigned)GRID) break;
                    __nanosleep(64);
                } while (true);
            }
            __syncthreads();                           // acquire visible block-wide

            const int base = b << 22;
            const int c0   = e0 & 63;                  // e0 multiple of 4
            atomicAdd(out + base + (id.x & ~63) + (c0 + 0), v.x);
            atomicAdd(out + base + (id.y & ~63) + (c0 + 1), v.y);
            atomicAdd(out + base + (id.z & ~63) + (c0 + 2), v.z);
            atomicAdd(out + base + (id.w & ~63) + (c0 + 3), v.w);
        }
    }
}

extern "C" void kernel_launch(void* const* d_in, const int* in_sizes, int n_in,
                              void* d_out, int out_size)
{
    const float* in  = (const float*)d_in[0];
    const int*   idx = (const int*)d_in[1];
    float*       out = (float*)d_out;

    reset_counters_kernel<<<1, 32>>>();
    unpool_persistent_kernel<<<GRID, BLOCK>>>(in, idx, out);
}

// round 8
// speedup vs baseline: 1.3256x; 1.3256x over previous
#include <cuda_runtime.h>
#include <cuda_bf16.h>
#include <cstdint>

// MaxUnpooling2DMod: out[b, y(idx), x(idx), c] += in[b,h,w,c]
//   in  [8,128,128,64] -> 2^23 floats, out [8,256,256,64] -> 2^25 floats
// decode: out_off = (b << 22) + (idx & ~63) + (lin & 63)
//
// PDL chain of 16 kernels: z0,s0,z1,s1,...  (z = zero slab, s = scatter batch)
//  - z_b: stores zeros, NO griddepcontrol.wait (untouched range), triggers
//         launch_dependents after its stores.
//  - s_b: triggers at ENTRY (releases z_{b+1} immediately), loads batch b,
//         griddepcontrol.wait (-> completion of z_b ONLY, the immediate
//         predecessor), then fire-and-forget atomics.
// Result: z_{b+1} runs under s_b, and s_{b+1} starts as soon as z_{b+1}
// finishes -> consecutive scatters' atomic drains overlap. All concurrent
// grids write disjoint slabs.

static constexpr int BLOCK = 256;

// ---- zero kernel: 16.8 MB slab ----
static constexpr int ZGRID     = 1024;
static constexpr int ZTHREADS  = ZGRID * BLOCK;           // 262144
static constexpr int SLAB_F4   = (1 << 22) / 4;           // 1,048,576
static constexpr int ZERO_PER_T = SLAB_F4 / ZTHREADS;     // 4

__global__ void __launch_bounds__(BLOCK)
zero_slab_kernel(float* __restrict__ out, int slab)
{
    const int t = blockIdx.x * BLOCK + threadIdx.x;
    float4* o4 = reinterpret_cast<float4*>(out) + (size_t)slab * SLAB_F4;
    const float4 z = make_float4(0.f, 0.f, 0.f, 0.f);
    #pragma unroll
    for (int j = 0; j < ZERO_PER_T; j++)
        o4[t + j * ZTHREADS] = z;
    // Release the dependent scatter only after this block's stores are issued.
    asm volatile("griddepcontrol.launch_dependents;" ::: "memory");
}

// ---- scatter kernel: batch b -> slab b ----
static constexpr int SGRID    = 2048;
__global__ void __launch_bounds__(BLOCK)
scatter_kernel(const float* __restrict__ in,
               const int*   __restrict__ idx,
               float*       __restrict__ out,
               int b)
{
    // Release the NEXT kernel (zero of slab b+1, disjoint) immediately.
    asm volatile("griddepcontrol.launch_dependents;" ::: "memory");

    const int t  = blockIdx.x * BLOCK + threadIdx.x;      // 524288 threads
    const int e0 = (b << 20) + (t << 1);                  // 2 elems/thread

    const float2 v  = __ldcs(reinterpret_cast<const float2*>(in)  + (e0 >> 1));
    const int2   id = __ldcs(reinterpret_cast<const int2*>(idx)   + (e0 >> 1));

    // Wait for immediate predecessor (zero_slab_kernel b) to complete:
    // slab b is fully zeroed and visible.
    asm volatile("griddepcontrol.wait;" ::: "memory");

    const int base = b << 22;
    const int c0   = e0 & 63;                             // e0 even
    atomicAdd(out + base + (id.x & ~63) + (c0 + 0), v.x);
    atomicAdd(out + base + (id.y & ~63) + (c0 + 1), v.y);
}

extern "C" void kernel_launch(void* const* d_in, const int* in_sizes, int n_in,
                              void* d_out, int out_size)
{
    const float* in  = (const float*)d_in[0];
    const int*   idx = (const int*)d_in[1];
    float*       out = (float*)d_out;

    cudaLaunchAttribute attrs[1];
    attrs[0].id = cudaLaunchAttributeProgrammaticStreamSerialization;
    attrs[0].val.programmaticStreamSerializationAllowed = 1;

    cudaLaunchConfig_t zcfg = {};
    zcfg.gridDim  = dim3(ZGRID, 1, 1);
    zcfg.blockDim = dim3(BLOCK, 1, 1);
    zcfg.stream   = 0;

    cudaLaunchConfig_t scfg = zcfg;
    scfg.gridDim = dim3(SGRID, 1, 1);

    for (int b = 0; b < 8; b++) {
        // z_b: first launch has no predecessor; all others opt in to early launch.
        zcfg.attrs    = (b == 0) ? nullptr : attrs;
        zcfg.numAttrs = (b == 0) ? 0 : 1;
        cudaLaunchKernelEx(&zcfg, zero_slab_kernel, out, b);

        scfg.attrs = attrs;  scfg.numAttrs = 1;
        cudaLaunchKernelEx(&scfg, scatter_kernel, in, idx, out, b);
    }
}